// round 2
// baseline (speedup 1.0000x reference)
#include <cuda_runtime.h>
#include <math.h>

#define Bn 4
#define CI 128
#define CO 128
#define Hn 128
#define Wn 128
#define HW (Hn*Wn)
#define KK 9
#define PIX 32

// ---------------- scratch (static device allocations, allowed) ----------------
__device__ __align__(16) float g_xT[Bn*HW*CI];      // x in NHWC          33.5 MB
__device__ __align__(16) float g_off[Bn*18*HW];     // offset conv output  4.7 MB
__device__ __align__(16) float g_wT[KK*CI*CO];      // w_dcn [k][c4][o][4] 0.6 MB
__device__ __align__(16) float g_conv[Bn*CO*HW];    // pre-BN output      33.5 MB
__device__ float g_scale[CO];
__device__ float g_shift[CO];

// ---------------- K1: NCHW -> NHWC transpose of x ----------------
__global__ void k_transpose_x(const float* __restrict__ in) {
    __shared__ float t[32][33];
    int wb = blockIdx.x * 32, cb = blockIdx.y * 32;
    int by = blockIdx.z;                 // b*Hn + y
    int b = by >> 7, y = by & 127;
    t[threadIdx.y][threadIdx.x] =
        in[((b*CI + cb + threadIdx.y)*Hn + y)*Wn + wb + threadIdx.x];
    __syncthreads();
    g_xT[(by*Wn + wb + threadIdx.y)*CI + cb + threadIdx.x] = t[threadIdx.x][threadIdx.y];
}

// ---------------- K2: w_dcn [o][c][k] -> [k][c>>2][o][c&3] ----------------
__global__ void k_transpose_w(const float* __restrict__ w) {
    int i = blockIdx.x * blockDim.x + threadIdx.x;
    if (i >= CO*CI*KK) return;
    int o = i / (CI*KK);
    int r = i % (CI*KK);
    int c = r / KK;
    int kk = r % KK;
    g_wT[((kk*(CI/4) + (c >> 2))*CO + o)*4 + (c & 3)] = w[i];
}

// ---------------- K3: offset conv (18 output channels, 3x3, pad 1) ----------------
__global__ __launch_bounds__(128) void k_offset_conv(
    const float* __restrict__ x, const float* __restrict__ w_off,
    const float* __restrict__ b_off) {
    __shared__ float sw[64*9*18];        // 41.5 KB chunk of weights
    int h = blockIdx.x, b = blockIdx.y;
    int w = threadIdx.x;

    float acc[18];
#pragma unroll
    for (int j = 0; j < 18; j++) acc[j] = 0.f;

    for (int c0 = 0; c0 < CI; c0 += 64) {
        __syncthreads();
        for (int e = threadIdx.x; e < 64*9*18; e += 128) {
            int cl = e / 162, r = e % 162, t = r / 18, j = r % 18;
            sw[e] = w_off[((j*CI + c0 + cl)*3 + t/3)*3 + t%3];
        }
        __syncthreads();
        for (int cl = 0; cl < 64; cl++) {
            const float* xp = x + (size_t)(b*CI + c0 + cl)*HW;
#pragma unroll
            for (int t = 0; t < 9; t++) {
                int yy = h + t/3 - 1;
                int xx = w + t%3 - 1;
                float xv = (yy >= 0 && yy < Hn && xx >= 0 && xx < Wn)
                         ? xp[yy*Wn + xx] : 0.f;
                const float* swp = &sw[(cl*9 + t)*18];
#pragma unroll
                for (int j = 0; j < 18; j++) acc[j] = fmaf(xv, swp[j], acc[j]);
            }
        }
    }
#pragma unroll
    for (int j = 0; j < 18; j++)
        g_off[((b*18 + j)*Hn + h)*Wn + w] = acc[j] + b_off[j];
}

// ---------------- K4: fused deformable sampling + GEMM ----------------
// grid (Wn/PIX, Hn, Bn); 128 threads; thread = output channel o.
__global__ __launch_bounds__(128) void k_main() {
    const int w0  = blockIdx.x * PIX;
    const int h   = blockIdx.y;
    const int b   = blockIdx.z;
    const int tid = threadIdx.x;
    const int o   = tid;

    __shared__ float sS[PIX][CI];     // sampled[pix][c]   16 KB
    __shared__ int   sIdx[4][PIX];
    __shared__ float sWt[4][PIX];

    float acc[PIX];
#pragma unroll
    for (int p = 0; p < PIX; p++) acc[p] = 0.f;

    for (int k = 0; k < KK; k++) {
        // --- per-pixel corner index/weight setup (32 threads) ---
        if (tid < PIX) {
            int w = w0 + tid;
            float dy = g_off[((b*18 + 2*k    )*Hn + h)*Wn + w];
            float dx = g_off[((b*18 + 2*k + 1)*Hn + h)*Wn + w];
            float ys = (float)(h - 1 + (k / 3)) + dy;
            float xs = (float)(w - 1 + (k % 3)) + dx;
            float y0f = floorf(ys), x0f = floorf(xs);
            float wy = ys - y0f, wx = xs - x0f;
            int y0 = (int)y0f, x0 = (int)x0f;
            int y1 = y0 + 1, x1 = x0 + 1;
            float vy0 = (y0 >= 0 && y0 < Hn) ? 1.f : 0.f;
            float vy1 = (y1 >= 0 && y1 < Hn) ? 1.f : 0.f;
            float vx0 = (x0 >= 0 && x0 < Wn) ? 1.f : 0.f;
            float vx1 = (x1 >= 0 && x1 < Wn) ? 1.f : 0.f;
            int y0c = min(max(y0, 0), Hn-1), y1c = min(max(y1, 0), Hn-1);
            int x0c = min(max(x0, 0), Wn-1), x1c = min(max(x1, 0), Wn-1);
            int base = b * HW;
            sIdx[0][tid] = (base + y0c*Wn + x0c)*CI;
            sIdx[1][tid] = (base + y0c*Wn + x1c)*CI;
            sIdx[2][tid] = (base + y1c*Wn + x0c)*CI;
            sIdx[3][tid] = (base + y1c*Wn + x1c)*CI;
            sWt[0][tid] = (1.f - wy)*(1.f - wx)*vy0*vx0;
            sWt[1][tid] = (1.f - wy)*wx       *vy0*vx1;
            sWt[2][tid] = wy       *(1.f - wx)*vy1*vx0;
            sWt[3][tid] = wy       *wx        *vy1*vx1;
        }
        __syncthreads();

        // --- sampling: warp = 4 pixels x 8 c-lanes (coalesced 128B per corner) ---
#pragma unroll
        for (int it = 0; it < 8; it++) {
            int cc  = (it >> 1) * 32;
            int pp  = (it & 1) * 16;
            int pix = pp + (tid >> 3);
            int c   = cc + (tid & 7) * 4;
            int i0 = sIdx[0][pix], i1 = sIdx[1][pix];
            int i2 = sIdx[2][pix], i3 = sIdx[3][pix];
            float w00 = sWt[0][pix], w01 = sWt[1][pix];
            float w10 = sWt[2][pix], w11 = sWt[3][pix];
            float4 p0 = *(const float4*)(g_xT + i0 + c);
            float4 p1 = *(const float4*)(g_xT + i1 + c);
            float4 p2 = *(const float4*)(g_xT + i2 + c);
            float4 p3 = *(const float4*)(g_xT + i3 + c);
            float4 v;
            v.x = w00*p0.x + w01*p1.x + w10*p2.x + w11*p3.x;
            v.y = w00*p0.y + w01*p1.y + w10*p2.y + w11*p3.y;
            v.z = w00*p0.z + w01*p1.z + w10*p2.z + w11*p3.z;
            v.w = w00*p0.w + w01*p1.w + w10*p2.w + w11*p3.w;
            *(float4*)(&sS[pix][c]) = v;
        }
        __syncthreads();

        // --- GEMM accumulate: thread o, 32 pixel accumulators ---
        const float4* wrow = (const float4*)(g_wT + (k*(CI/4))*CO*4) + o;
#pragma unroll 2
        for (int c4 = 0; c4 < CI/4; c4++) {
            float4 wv = wrow[c4*CO];
#pragma unroll
            for (int p = 0; p < PIX; p++) {
                float4 sv = *(const float4*)(&sS[p][c4*4]);
                acc[p] = fmaf(wv.x, sv.x, acc[p]);
                acc[p] = fmaf(wv.y, sv.y, acc[p]);
                acc[p] = fmaf(wv.z, sv.z, acc[p]);
                acc[p] = fmaf(wv.w, sv.w, acc[p]);
            }
        }
    }

    float* dst = g_conv + ((size_t)(b*CO + o)*Hn + h)*Wn + w0;
#pragma unroll
    for (int p4 = 0; p4 < PIX/4; p4++)
        *(float4*)(dst + p4*4) =
            make_float4(acc[p4*4], acc[p4*4+1], acc[p4*4+2], acc[p4*4+3]);
}

// ---------------- K5: BN stats per channel ----------------
__global__ void k_bn_stats(const float* __restrict__ gamma,
                           const float* __restrict__ beta) {
    int o = blockIdx.x, tid = threadIdx.x;   // 256 threads
    float s = 0.f, s2 = 0.f;
    for (int b = 0; b < Bn; b++) {
        const float* p = g_conv + (size_t)(b*CO + o)*HW;
        for (int i = tid; i < HW; i += 256) {
            float v = p[i];
            s += v;
            s2 = fmaf(v, v, s2);
        }
    }
    __shared__ float rs[8], rs2[8];
#pragma unroll
    for (int off = 16; off; off >>= 1) {
        s  += __shfl_down_sync(0xffffffffu, s,  off);
        s2 += __shfl_down_sync(0xffffffffu, s2, off);
    }
    if ((tid & 31) == 0) { rs[tid >> 5] = s; rs2[tid >> 5] = s2; }
    __syncthreads();
    if (tid < 32) {
        s  = (tid < 8) ? rs[tid]  : 0.f;
        s2 = (tid < 8) ? rs2[tid] : 0.f;
#pragma unroll
        for (int off = 4; off; off >>= 1) {
            s  += __shfl_down_sync(0xffffffffu, s,  off);
            s2 += __shfl_down_sync(0xffffffffu, s2, off);
        }
        if (tid == 0) {
            float inv_n = 1.f / (float)(Bn*HW);
            float mean = s * inv_n;
            float var  = s2 * inv_n - mean*mean;
            float r = 1.f / sqrtf(var + 0.001f);
            float sc = gamma[o] * r;
            g_scale[o] = sc;
            g_shift[o] = beta[o] - mean*sc;
        }
    }
}

// ---------------- K6: apply BN + ReLU ----------------
__global__ void k_bn_apply(float* __restrict__ out) {
    int i = blockIdx.x * blockDim.x + threadIdx.x;   // float4 index
    int ch = (i >> 12) & 127;                        // plane = 16384 elems = 4096 float4
    float4 v = ((const float4*)g_conv)[i];
    float sc = g_scale[ch], sh = g_shift[ch];
    v.x = fmaxf(fmaf(v.x, sc, sh), 0.f);
    v.y = fmaxf(fmaf(v.y, sc, sh), 0.f);
    v.z = fmaxf(fmaf(v.z, sc, sh), 0.f);
    v.w = fmaxf(fmaf(v.w, sc, sh), 0.f);
    ((float4*)out)[i] = v;
}

// ---------------- launch ----------------
extern "C" void kernel_launch(void* const* d_in, const int* in_sizes, int n_in,
                              void* d_out, int out_size) {
    const float* x     = (const float*)d_in[0];
    const float* w_off = (const float*)d_in[1];
    const float* b_off = (const float*)d_in[2];
    const float* w_dcn = (const float*)d_in[3];
    const float* gamma = (const float*)d_in[4];
    const float* beta  = (const float*)d_in[5];
    float* out = (float*)d_out;

    k_transpose_x<<<dim3(Wn/32, CI/32, Bn*Hn), dim3(32, 32)>>>(x);
    k_transpose_w<<<(CO*CI*KK + 255)/256, 256>>>(w_dcn);
    k_offset_conv<<<dim3(Hn, Bn), 128>>>(x, w_off, b_off);
    k_main<<<dim3(Wn/PIX, Hn, Bn), 128>>>();
    k_bn_stats<<<CO, 256>>>(gamma, beta);
    k_bn_apply<<<(Bn*CO*HW/4)/256, 256>>>(out);
}

// round 3
// speedup vs baseline: 1.1212x; 1.1212x over previous
#include <cuda_runtime.h>
#include <math.h>

#define Bn 4
#define CI 128
#define CO 128
#define Hn 128
#define Wn 128
#define HW (Hn*Wn)
#define KK 9
#define PIX 32

// ---------------- scratch (static device allocations, allowed) ----------------
__device__ __align__(16) float g_xT[Bn*HW*CI];       // x in NHWC          33.5 MB
__device__ __align__(16) float g_offp[2][Bn*18*HW];  // partial offset conv  9.4 MB
__device__ __align__(16) float g_wT[KK*CI*CO];       // w_dcn [k][c4][o][4] 0.6 MB
__device__ __align__(16) float g_conv[Bn*CO*HW];     // pre-BN output      33.5 MB
__device__ float g_scale[CO];
__device__ float g_shift[CO];

// ---------------- K1: NCHW -> NHWC transpose of x ----------------
__global__ void k_transpose_x(const float* __restrict__ in) {
    __shared__ float t[32][33];
    int wb = blockIdx.x * 32, cb = blockIdx.y * 32;
    int by = blockIdx.z;                 // b*Hn + y
    int b = by >> 7, y = by & 127;
    t[threadIdx.y][threadIdx.x] =
        in[((b*CI + cb + threadIdx.y)*Hn + y)*Wn + wb + threadIdx.x];
    __syncthreads();
    g_xT[(by*Wn + wb + threadIdx.y)*CI + cb + threadIdx.x] = t[threadIdx.x][threadIdx.y];
}

// ---------------- K2: w_dcn [o][c][k] -> [k][c>>2][o][c&3] ----------------
__global__ void k_transpose_w(const float* __restrict__ w) {
    int i = blockIdx.x * blockDim.x + threadIdx.x;
    if (i >= CO*CI*KK) return;
    int o = i / (CI*KK);
    int r = i % (CI*KK);
    int c = r / KK;
    int kk = r % KK;
    g_wT[((kk*(CI/4) + (c >> 2))*CO + o)*4 + (c & 3)] = w[i];
}

// ---------------- K3: offset conv (18 out ch, 3x3, pad 1), CI split over z ----------------
__global__ __launch_bounds__(128) void k_offset_conv(
    const float* __restrict__ x, const float* __restrict__ w_off,
    const float* __restrict__ b_off) {
    __shared__ float sw[64*9*18];        // 41.5 KB chunk of weights
    int h = blockIdx.x, b = blockIdx.y, z = blockIdx.z;
    int c0 = z * 64;
    int w = threadIdx.x;

    float acc[18];
#pragma unroll
    for (int j = 0; j < 18; j++) acc[j] = 0.f;

    for (int e = threadIdx.x; e < 64*9*18; e += 128) {
        int cl = e / 162, r = e % 162, t = r / 18, j = r % 18;
        sw[e] = w_off[((j*CI + c0 + cl)*3 + t/3)*3 + t%3];
    }
    __syncthreads();
    for (int cl = 0; cl < 64; cl++) {
        const float* xp = x + (size_t)(b*CI + c0 + cl)*HW;
#pragma unroll
        for (int t = 0; t < 9; t++) {
            int yy = h + t/3 - 1;
            int xx = w + t%3 - 1;
            float xv = (yy >= 0 && yy < Hn && xx >= 0 && xx < Wn)
                     ? xp[yy*Wn + xx] : 0.f;
            const float* swp = &sw[(cl*9 + t)*18];
#pragma unroll
            for (int j = 0; j < 18; j++) acc[j] = fmaf(xv, swp[j], acc[j]);
        }
    }
#pragma unroll
    for (int j = 0; j < 18; j++)
        g_offp[z][((b*18 + j)*Hn + h)*Wn + w] = acc[j] + (z == 0 ? b_off[j] : 0.f);
}

// ---------------- K4: fused deformable sampling + GEMM ----------------
// grid (Wn/PIX, Hn, Bn); 128 threads.
// GEMM blocking: thread owns 4 output channels (og+32j) x 8 pixels (pg*8..pg*8+7).
__global__ __launch_bounds__(128) void k_main() {
    const int w0  = blockIdx.x * PIX;
    const int h   = blockIdx.y;
    const int b   = blockIdx.z;
    const int tid = threadIdx.x;
    const int og  = tid & 31;
    const int pg  = tid >> 5;

    __shared__ float sS[PIX][CI];     // sampled[pix][c]   16 KB
    __shared__ int   sIdx[4][PIX];
    __shared__ float sWt[4][PIX];

    float acc0[8], acc1[8], acc2[8], acc3[8];
#pragma unroll
    for (int p = 0; p < 8; p++) { acc0[p]=0.f; acc1[p]=0.f; acc2[p]=0.f; acc3[p]=0.f; }

    for (int k = 0; k < KK; k++) {
        // --- per-pixel corner index/weight setup (32 threads) ---
        if (tid < PIX) {
            int w = w0 + tid;
            int oidx = ((b*18 + 2*k)*Hn + h)*Wn + w;
            float dy = g_offp[0][oidx]      + g_offp[1][oidx];
            float dx = g_offp[0][oidx + HW] + g_offp[1][oidx + HW];
            float ys = (float)(h - 1 + (k / 3)) + dy;
            float xs = (float)(w - 1 + (k % 3)) + dx;
            float y0f = floorf(ys), x0f = floorf(xs);
            float wy = ys - y0f, wx = xs - x0f;
            int y0 = (int)y0f, x0 = (int)x0f;
            int y1 = y0 + 1, x1 = x0 + 1;
            float vy0 = (y0 >= 0 && y0 < Hn) ? 1.f : 0.f;
            float vy1 = (y1 >= 0 && y1 < Hn) ? 1.f : 0.f;
            float vx0 = (x0 >= 0 && x0 < Wn) ? 1.f : 0.f;
            float vx1 = (x1 >= 0 && x1 < Wn) ? 1.f : 0.f;
            int y0c = min(max(y0, 0), Hn-1), y1c = min(max(y1, 0), Hn-1);
            int x0c = min(max(x0, 0), Wn-1), x1c = min(max(x1, 0), Wn-1);
            int base = b * HW;
            sIdx[0][tid] = (base + y0c*Wn + x0c)*CI;
            sIdx[1][tid] = (base + y0c*Wn + x1c)*CI;
            sIdx[2][tid] = (base + y1c*Wn + x0c)*CI;
            sIdx[3][tid] = (base + y1c*Wn + x1c)*CI;
            sWt[0][tid] = (1.f - wy)*(1.f - wx)*vy0*vx0;
            sWt[1][tid] = (1.f - wy)*wx       *vy0*vx1;
            sWt[2][tid] = wy       *(1.f - wx)*vy1*vx0;
            sWt[3][tid] = wy       *wx        *vy1*vx1;
        }
        __syncthreads();

        // --- sampling: warp = 4 pixels x 8 c-lanes (coalesced 128B per corner) ---
#pragma unroll
        for (int it = 0; it < 8; it++) {
            int cc  = (it >> 1) * 32;
            int pp  = (it & 1) * 16;
            int pix = pp + (tid >> 3);
            int c   = cc + (tid & 7) * 4;
            int i0 = sIdx[0][pix], i1 = sIdx[1][pix];
            int i2 = sIdx[2][pix], i3 = sIdx[3][pix];
            float w00 = sWt[0][pix], w01 = sWt[1][pix];
            float w10 = sWt[2][pix], w11 = sWt[3][pix];
            float4 p0 = *(const float4*)(g_xT + i0 + c);
            float4 p1 = *(const float4*)(g_xT + i1 + c);
            float4 p2 = *(const float4*)(g_xT + i2 + c);
            float4 p3 = *(const float4*)(g_xT + i3 + c);
            float4 v;
            v.x = w00*p0.x + w01*p1.x + w10*p2.x + w11*p3.x;
            v.y = w00*p0.y + w01*p1.y + w10*p2.y + w11*p3.y;
            v.z = w00*p0.z + w01*p1.z + w10*p2.z + w11*p3.z;
            v.w = w00*p0.w + w01*p1.w + w10*p2.w + w11*p3.w;
            *(float4*)(&sS[pix][c]) = v;
        }
        __syncthreads();

        // --- GEMM accumulate: 4 channels x 8 pixels, 16 FMA per LDS.128 ---
        const float4* wbase = (const float4*)g_wT + k*(CI/4)*CO;
        const float*  srow  = &sS[pg*8][0];
#pragma unroll 4
        for (int c4 = 0; c4 < CI/4; c4++) {
            float4 wv0 = wbase[c4*CO + og];
            float4 wv1 = wbase[c4*CO + og + 32];
            float4 wv2 = wbase[c4*CO + og + 64];
            float4 wv3 = wbase[c4*CO + og + 96];
#pragma unroll
            for (int p = 0; p < 8; p++) {
                float4 sv = *(const float4*)(srow + p*CI + c4*4);
                acc0[p] = fmaf(wv0.x, sv.x, acc0[p]);
                acc0[p] = fmaf(wv0.y, sv.y, acc0[p]);
                acc0[p] = fmaf(wv0.z, sv.z, acc0[p]);
                acc0[p] = fmaf(wv0.w, sv.w, acc0[p]);
                acc1[p] = fmaf(wv1.x, sv.x, acc1[p]);
                acc1[p] = fmaf(wv1.y, sv.y, acc1[p]);
                acc1[p] = fmaf(wv1.z, sv.z, acc1[p]);
                acc1[p] = fmaf(wv1.w, sv.w, acc1[p]);
                acc2[p] = fmaf(wv2.x, sv.x, acc2[p]);
                acc2[p] = fmaf(wv2.y, sv.y, acc2[p]);
                acc2[p] = fmaf(wv2.z, sv.z, acc2[p]);
                acc2[p] = fmaf(wv2.w, sv.w, acc2[p]);
                acc3[p] = fmaf(wv3.x, sv.x, acc3[p]);
                acc3[p] = fmaf(wv3.y, sv.y, acc3[p]);
                acc3[p] = fmaf(wv3.z, sv.z, acc3[p]);
                acc3[p] = fmaf(wv3.w, sv.w, acc3[p]);
            }
        }
    }

    // write out: 4 channels x 8 pixels per thread
    size_t pbase = (size_t)(b*CO)*HW + h*Wn + w0 + pg*8;
    float* d0 = g_conv + pbase + (size_t)(og      )*HW;
    float* d1 = g_conv + pbase + (size_t)(og + 32 )*HW;
    float* d2 = g_conv + pbase + (size_t)(og + 64 )*HW;
    float* d3 = g_conv + pbase + (size_t)(og + 96 )*HW;
    *(float4*)(d0)     = make_float4(acc0[0],acc0[1],acc0[2],acc0[3]);
    *(float4*)(d0 + 4) = make_float4(acc0[4],acc0[5],acc0[6],acc0[7]);
    *(float4*)(d1)     = make_float4(acc1[0],acc1[1],acc1[2],acc1[3]);
    *(float4*)(d1 + 4) = make_float4(acc1[4],acc1[5],acc1[6],acc1[7]);
    *(float4*)(d2)     = make_float4(acc2[0],acc2[1],acc2[2],acc2[3]);
    *(float4*)(d2 + 4) = make_float4(acc2[4],acc2[5],acc2[6],acc2[7]);
    *(float4*)(d3)     = make_float4(acc3[0],acc3[1],acc3[2],acc3[3]);
    *(float4*)(d3 + 4) = make_float4(acc3[4],acc3[5],acc3[6],acc3[7]);
}

// ---------------- K5: BN stats per channel ----------------
__global__ void k_bn_stats(const float* __restrict__ gamma,
                           const float* __restrict__ beta) {
    int o = blockIdx.x, tid = threadIdx.x;   // 256 threads
    float s = 0.f, s2 = 0.f;
    for (int b = 0; b < Bn; b++) {
        const float* p = g_conv + (size_t)(b*CO + o)*HW;
        for (int i = tid; i < HW; i += 256) {
            float v = p[i];
            s += v;
            s2 = fmaf(v, v, s2);
        }
    }
    __shared__ float rs[8], rs2[8];
#pragma unroll
    for (int off = 16; off; off >>= 1) {
        s  += __shfl_down_sync(0xffffffffu, s,  off);
        s2 += __shfl_down_sync(0xffffffffu, s2, off);
    }
    if ((tid & 31) == 0) { rs[tid >> 5] = s; rs2[tid >> 5] = s2; }
    __syncthreads();
    if (tid < 32) {
        s  = (tid < 8) ? rs[tid]  : 0.f;
        s2 = (tid < 8) ? rs2[tid] : 0.f;
#pragma unroll
        for (int off = 4; off; off >>= 1) {
            s  += __shfl_down_sync(0xffffffffu, s,  off);
            s2 += __shfl_down_sync(0xffffffffu, s2, off);
        }
        if (tid == 0) {
            float inv_n = 1.f / (float)(Bn*HW);
            float mean = s * inv_n;
            float var  = s2 * inv_n - mean*mean;
            float r = 1.f / sqrtf(var + 0.001f);
            float sc = gamma[o] * r;
            g_scale[o] = sc;
            g_shift[o] = beta[o] - mean*sc;
        }
    }
}

// ---------------- K6: apply BN + ReLU ----------------
__global__ void k_bn_apply(float* __restrict__ out) {
    int i = blockIdx.x * blockDim.x + threadIdx.x;   // float4 index
    int ch = (i >> 12) & 127;                        // plane = 16384 elems = 4096 float4
    float4 v = ((const float4*)g_conv)[i];
    float sc = g_scale[ch], sh = g_shift[ch];
    v.x = fmaxf(fmaf(v.x, sc, sh), 0.f);
    v.y = fmaxf(fmaf(v.y, sc, sh), 0.f);
    v.z = fmaxf(fmaf(v.z, sc, sh), 0.f);
    v.w = fmaxf(fmaf(v.w, sc, sh), 0.f);
    ((float4*)out)[i] = v;
}

// ---------------- launch ----------------
extern "C" void kernel_launch(void* const* d_in, const int* in_sizes, int n_in,
                              void* d_out, int out_size) {
    const float* x     = (const float*)d_in[0];
    const float* w_off = (const float*)d_in[1];
    const float* b_off = (const float*)d_in[2];
    const float* w_dcn = (const float*)d_in[3];
    const float* gamma = (const float*)d_in[4];
    const float* beta  = (const float*)d_in[5];
    float* out = (float*)d_out;

    k_transpose_x<<<dim3(Wn/32, CI/32, Bn*Hn), dim3(32, 32)>>>(x);
    k_transpose_w<<<(CO*CI*KK + 255)/256, 256>>>(w_dcn);
    k_offset_conv<<<dim3(Hn, Bn, 2), 128>>>(x, w_off, b_off);
    k_main<<<dim3(Wn/PIX, Hn, Bn), 128>>>();
    k_bn_stats<<<CO, 256>>>(gamma, beta);
    k_bn_apply<<<(Bn*CO*HW/4)/256, 256>>>(out);
}

// round 4
// speedup vs baseline: 1.4173x; 1.2641x over previous
#include <cuda_runtime.h>
#include <math.h>

#define Bn 4
#define CI 128
#define CO 128
#define Hn 128
#define Wn 128
#define HW (Hn*Wn)
#define KK 9
#define PIX 32

// packed fp32x2 helpers (Blackwell sm_103a)
#define PACKF2(d, a, b) asm("mov.b64 %0, {%1, %2};" : "=l"(d) : "f"(a), "f"(b))
#define FMAF2(d, a, b, c) asm("fma.rn.f32x2 %0, %1, %2, %3;" : "=l"(d) : "l"(a), "l"(b), "l"(c))
union F2U { unsigned long long u; float2 f; };

// ---------------- scratch (static device allocations, allowed) ----------------
__device__ __align__(16) float g_xT[Bn*HW*CI];       // x in NHWC          33.5 MB
__device__ __align__(16) float g_offp[2][Bn*18*HW];  // partial offset conv  9.4 MB
__device__ __align__(16) float g_wT[KK*CI*CO];       // w_dcn [k][c4][o][4] 0.6 MB
__device__ __align__(16) float g_conv[Bn*CO*HW];     // pre-BN output      33.5 MB
__device__ float g_scale[CO];
__device__ float g_shift[CO];

// ---------------- K1: NCHW -> NHWC transpose of x ----------------
__global__ void k_transpose_x(const float* __restrict__ in) {
    __shared__ float t[32][33];
    int wb = blockIdx.x * 32, cb = blockIdx.y * 32;
    int by = blockIdx.z;                 // b*Hn + y
    int b = by >> 7, y = by & 127;
    t[threadIdx.y][threadIdx.x] =
        in[((b*CI + cb + threadIdx.y)*Hn + y)*Wn + wb + threadIdx.x];
    __syncthreads();
    g_xT[(by*Wn + wb + threadIdx.y)*CI + cb + threadIdx.x] = t[threadIdx.x][threadIdx.y];
}

// ---------------- K2: w_dcn [o][c][k] -> [k][c>>2][o][c&3] ----------------
__global__ void k_transpose_w(const float* __restrict__ w) {
    int i = blockIdx.x * blockDim.x + threadIdx.x;
    if (i >= CO*CI*KK) return;
    int o = i / (CI*KK);
    int r = i % (CI*KK);
    int c = r / KK;
    int kk = r % KK;
    g_wT[((kk*(CI/4) + (c >> 2))*CO + o)*4 + (c & 3)] = w[i];
}

// ---------------- K3: offset conv (18 out ch, 3x3, pad 1), CI split over z ----------------
__global__ __launch_bounds__(128) void k_offset_conv(
    const float* __restrict__ x, const float* __restrict__ w_off,
    const float* __restrict__ b_off) {
    __shared__ __align__(16) float sw[64*9*18];      // 41.5 KB chunk of weights
    int h = blockIdx.x, b = blockIdx.y, z = blockIdx.z;
    int c0 = z * 64;
    int w = threadIdx.x;

    unsigned long long acc2[9];
#pragma unroll
    for (int j = 0; j < 9; j++) acc2[j] = 0ull;      // == (0.0f, 0.0f)

    for (int e = threadIdx.x; e < 64*9*18; e += 128) {
        int cl = e / 162, r = e % 162, t = r / 18, j = r % 18;
        sw[e] = w_off[((j*CI + c0 + cl)*3 + t/3)*3 + t%3];
    }
    __syncthreads();
    for (int cl = 0; cl < 64; cl++) {
        const float* xp = x + (size_t)(b*CI + c0 + cl)*HW;
#pragma unroll
        for (int t = 0; t < 9; t++) {
            int yy = h + t/3 - 1;
            int xx = w + t%3 - 1;
            float xv = (yy >= 0 && yy < Hn && xx >= 0 && xx < Wn)
                     ? xp[yy*Wn + xx] : 0.f;
            unsigned long long xv2;
            PACKF2(xv2, xv, xv);
            // (cl*9+t)*18 floats = 72B units -> 8B aligned
            const unsigned long long* swp =
                (const unsigned long long*)&sw[(cl*9 + t)*18];
#pragma unroll
            for (int j = 0; j < 9; j++) FMAF2(acc2[j], xv2, swp[j], acc2[j]);
        }
    }
#pragma unroll
    for (int jj = 0; jj < 9; jj++) {
        F2U u; u.u = acc2[jj];
        float b0 = (z == 0) ? b_off[2*jj]     : 0.f;
        float b1 = (z == 0) ? b_off[2*jj + 1] : 0.f;
        g_offp[z][((b*18 + 2*jj    )*Hn + h)*Wn + w] = u.f.x + b0;
        g_offp[z][((b*18 + 2*jj + 1)*Hn + h)*Wn + w] = u.f.y + b1;
    }
}

// ---------------- K4: fused deformable sampling + GEMM (f32x2) ----------------
// grid (Wn/PIX, Hn, Bn); 128 threads.
// thread owns 4 out channels (og+32i) x 8 pixels (pg*8..pg*8+7) as 4 f32x2 pairs.
__global__ __launch_bounds__(128) void k_main() {
    const int w0  = blockIdx.x * PIX;
    const int h   = blockIdx.y;
    const int b   = blockIdx.z;
    const int tid = threadIdx.x;
    const int og  = tid & 31;
    const int pg  = tid >> 5;

    __shared__ __align__(16) float sT[CI][PIX + 2];   // sampled, transposed [c][pix]
    __shared__ int   sIdx[4][PIX];
    __shared__ float sWt[4][PIX];

    unsigned long long acc0[4], acc1[4], acc2[4], acc3[4];
#pragma unroll
    for (int p = 0; p < 4; p++) { acc0[p]=0ull; acc1[p]=0ull; acc2[p]=0ull; acc3[p]=0ull; }

    for (int k = 0; k < KK; k++) {
        // --- per-pixel corner index/weight setup (32 threads) ---
        if (tid < PIX) {
            int w = w0 + tid;
            int oidx = ((b*18 + 2*k)*Hn + h)*Wn + w;
            float dy = g_offp[0][oidx]      + g_offp[1][oidx];
            float dx = g_offp[0][oidx + HW] + g_offp[1][oidx + HW];
            float ys = (float)(h - 1 + (k / 3)) + dy;
            float xs = (float)(w - 1 + (k % 3)) + dx;
            float y0f = floorf(ys), x0f = floorf(xs);
            float wy = ys - y0f, wx = xs - x0f;
            int y0 = (int)y0f, x0 = (int)x0f;
            int y1 = y0 + 1, x1 = x0 + 1;
            float vy0 = (y0 >= 0 && y0 < Hn) ? 1.f : 0.f;
            float vy1 = (y1 >= 0 && y1 < Hn) ? 1.f : 0.f;
            float vx0 = (x0 >= 0 && x0 < Wn) ? 1.f : 0.f;
            float vx1 = (x1 >= 0 && x1 < Wn) ? 1.f : 0.f;
            int y0c = min(max(y0, 0), Hn-1), y1c = min(max(y1, 0), Hn-1);
            int x0c = min(max(x0, 0), Wn-1), x1c = min(max(x1, 0), Wn-1);
            int base = b * HW;
            sIdx[0][tid] = (base + y0c*Wn + x0c)*CI;
            sIdx[1][tid] = (base + y0c*Wn + x1c)*CI;
            sIdx[2][tid] = (base + y1c*Wn + x0c)*CI;
            sIdx[3][tid] = (base + y1c*Wn + x1c)*CI;
            sWt[0][tid] = (1.f - wy)*(1.f - wx)*vy0*vx0;
            sWt[1][tid] = (1.f - wy)*wx       *vy0*vx1;
            sWt[2][tid] = wy       *(1.f - wx)*vy1*vx0;
            sWt[3][tid] = wy       *wx        *vy1*vx1;
        }
        __syncthreads();

        // --- sampling: warp = 4 pixels x 8 c-lanes (coalesced 128B per corner) ---
#pragma unroll
        for (int it = 0; it < 8; it++) {
            int cc  = (it >> 1) * 32;
            int pp  = (it & 1) * 16;
            int pix = pp + (tid >> 3);
            int c   = cc + (tid & 7) * 4;
            int i0 = sIdx[0][pix], i1 = sIdx[1][pix];
            int i2 = sIdx[2][pix], i3 = sIdx[3][pix];
            float w00 = sWt[0][pix], w01 = sWt[1][pix];
            float w10 = sWt[2][pix], w11 = sWt[3][pix];
            float4 p0 = *(const float4*)(g_xT + i0 + c);
            float4 p1 = *(const float4*)(g_xT + i1 + c);
            float4 p2 = *(const float4*)(g_xT + i2 + c);
            float4 p3 = *(const float4*)(g_xT + i3 + c);
            sT[c+0][pix] = w00*p0.x + w01*p1.x + w10*p2.x + w11*p3.x;
            sT[c+1][pix] = w00*p0.y + w01*p1.y + w10*p2.y + w11*p3.y;
            sT[c+2][pix] = w00*p0.z + w01*p1.z + w10*p2.z + w11*p3.z;
            sT[c+3][pix] = w00*p0.w + w01*p1.w + w10*p2.w + w11*p3.w;
        }
        __syncthreads();

        // --- GEMM accumulate: 4 channels x 4 pixel-pairs via fma.rn.f32x2 ---
        const float4* wbase = (const float4*)g_wT + k*(CI/4)*CO;
#pragma unroll 2
        for (int c4 = 0; c4 < CI/4; c4++) {
            float4 q0 = wbase[c4*CO + og];
            float4 q1 = wbase[c4*CO + og + 32];
            float4 q2 = wbase[c4*CO + og + 64];
            float4 q3 = wbase[c4*CO + og + 96];
#pragma unroll
            for (int j = 0; j < 4; j++) {
                const float* srow = &sT[c4*4 + j][pg*8];   // 8B aligned (34*c + 8*pg even)
                unsigned long long s0 = *(const unsigned long long*)(srow + 0);
                unsigned long long s1 = *(const unsigned long long*)(srow + 2);
                unsigned long long s2 = *(const unsigned long long*)(srow + 4);
                unsigned long long s3 = *(const unsigned long long*)(srow + 6);
                float f0 = (j==0) ? q0.x : (j==1) ? q0.y : (j==2) ? q0.z : q0.w;
                float f1 = (j==0) ? q1.x : (j==1) ? q1.y : (j==2) ? q1.z : q1.w;
                float f2 = (j==0) ? q2.x : (j==1) ? q2.y : (j==2) ? q2.z : q2.w;
                float f3 = (j==0) ? q3.x : (j==1) ? q3.y : (j==2) ? q3.z : q3.w;
                unsigned long long W0, W1, W2, W3;
                PACKF2(W0, f0, f0);
                PACKF2(W1, f1, f1);
                PACKF2(W2, f2, f2);
                PACKF2(W3, f3, f3);
                FMAF2(acc0[0], W0, s0, acc0[0]);
                FMAF2(acc0[1], W0, s1, acc0[1]);
                FMAF2(acc0[2], W0, s2, acc0[2]);
                FMAF2(acc0[3], W0, s3, acc0[3]);
                FMAF2(acc1[0], W1, s0, acc1[0]);
                FMAF2(acc1[1], W1, s1, acc1[1]);
                FMAF2(acc1[2], W1, s2, acc1[2]);
                FMAF2(acc1[3], W1, s3, acc1[3]);
                FMAF2(acc2[0], W2, s0, acc2[0]);
                FMAF2(acc2[1], W2, s1, acc2[1]);
                FMAF2(acc2[2], W2, s2, acc2[2]);
                FMAF2(acc2[3], W2, s3, acc2[3]);
                FMAF2(acc3[0], W3, s0, acc3[0]);
                FMAF2(acc3[1], W3, s1, acc3[1]);
                FMAF2(acc3[2], W3, s2, acc3[2]);
                FMAF2(acc3[3], W3, s3, acc3[3]);
            }
        }
    }

    // write out: 4 channels x 8 pixels per thread
    size_t pbase = (size_t)(b*CO)*HW + h*Wn + w0 + pg*8;
    F2U u0, u1;
    float* d0 = g_conv + pbase + (size_t)(og      )*HW;
    float* d1 = g_conv + pbase + (size_t)(og + 32 )*HW;
    float* d2 = g_conv + pbase + (size_t)(og + 64 )*HW;
    float* d3 = g_conv + pbase + (size_t)(og + 96 )*HW;
    u0.u = acc0[0]; u1.u = acc0[1];
    *(float4*)(d0)     = make_float4(u0.f.x, u0.f.y, u1.f.x, u1.f.y);
    u0.u = acc0[2]; u1.u = acc0[3];
    *(float4*)(d0 + 4) = make_float4(u0.f.x, u0.f.y, u1.f.x, u1.f.y);
    u0.u = acc1[0]; u1.u = acc1[1];
    *(float4*)(d1)     = make_float4(u0.f.x, u0.f.y, u1.f.x, u1.f.y);
    u0.u = acc1[2]; u1.u = acc1[3];
    *(float4*)(d1 + 4) = make_float4(u0.f.x, u0.f.y, u1.f.x, u1.f.y);
    u0.u = acc2[0]; u1.u = acc2[1];
    *(float4*)(d2)     = make_float4(u0.f.x, u0.f.y, u1.f.x, u1.f.y);
    u0.u = acc2[2]; u1.u = acc2[3];
    *(float4*)(d2 + 4) = make_float4(u0.f.x, u0.f.y, u1.f.x, u1.f.y);
    u0.u = acc3[0]; u1.u = acc3[1];
    *(float4*)(d3)     = make_float4(u0.f.x, u0.f.y, u1.f.x, u1.f.y);
    u0.u = acc3[2]; u1.u = acc3[3];
    *(float4*)(d3 + 4) = make_float4(u0.f.x, u0.f.y, u1.f.x, u1.f.y);
}

// ---------------- K5: BN stats per channel ----------------
__global__ void k_bn_stats(const float* __restrict__ gamma,
                           const float* __restrict__ beta) {
    int o = blockIdx.x, tid = threadIdx.x;   // 256 threads
    float s = 0.f, s2 = 0.f;
    for (int b = 0; b < Bn; b++) {
        const float* p = g_conv + (size_t)(b*CO + o)*HW;
        for (int i = tid; i < HW; i += 256) {
            float v = p[i];
            s += v;
            s2 = fmaf(v, v, s2);
        }
    }
    __shared__ float rs[8], rs2[8];
#pragma unroll
    for (int off = 16; off; off >>= 1) {
        s  += __shfl_down_sync(0xffffffffu, s,  off);
        s2 += __shfl_down_sync(0xffffffffu, s2, off);
    }
    if ((tid & 31) == 0) { rs[tid >> 5] = s; rs2[tid >> 5] = s2; }
    __syncthreads();
    if (tid < 32) {
        s  = (tid < 8) ? rs[tid]  : 0.f;
        s2 = (tid < 8) ? rs2[tid] : 0.f;
#pragma unroll
        for (int off = 4; off; off >>= 1) {
            s  += __shfl_down_sync(0xffffffffu, s,  off);
            s2 += __shfl_down_sync(0xffffffffu, s2, off);
        }
        if (tid == 0) {
            float inv_n = 1.f / (float)(Bn*HW);
            float mean = s * inv_n;
            float var  = s2 * inv_n - mean*mean;
            float r = 1.f / sqrtf(var + 0.001f);
            float sc = gamma[o] * r;
            g_scale[o] = sc;
            g_shift[o] = beta[o] - mean*sc;
        }
    }
}

// ---------------- K6: apply BN + ReLU ----------------
__global__ void k_bn_apply(float* __restrict__ out) {
    int i = blockIdx.x * blockDim.x + threadIdx.x;   // float4 index
    int ch = (i >> 12) & 127;                        // plane = 16384 elems = 4096 float4
    float4 v = ((const float4*)g_conv)[i];
    float sc = g_scale[ch], sh = g_shift[ch];
    v.x = fmaxf(fmaf(v.x, sc, sh), 0.f);
    v.y = fmaxf(fmaf(v.y, sc, sh), 0.f);
    v.z = fmaxf(fmaf(v.z, sc, sh), 0.f);
    v.w = fmaxf(fmaf(v.w, sc, sh), 0.f);
    ((float4*)out)[i] = v;
}

// ---------------- launch ----------------
extern "C" void kernel_launch(void* const* d_in, const int* in_sizes, int n_in,
                              void* d_out, int out_size) {
    const float* x     = (const float*)d_in[0];
    const float* w_off = (const float*)d_in[1];
    const float* b_off = (const float*)d_in[2];
    const float* w_dcn = (const float*)d_in[3];
    const float* gamma = (const float*)d_in[4];
    const float* beta  = (const float*)d_in[5];
    float* out = (float*)d_out;

    k_transpose_x<<<dim3(Wn/32, CI/32, Bn*Hn), dim3(32, 32)>>>(x);
    k_transpose_w<<<(CO*CI*KK + 255)/256, 256>>>(w_dcn);
    k_offset_conv<<<dim3(Hn, Bn, 2), 128>>>(x, w_off, b_off);
    k_main<<<dim3(Wn/PIX, Hn, Bn), 128>>>();
    k_bn_stats<<<CO, 256>>>(gamma, beta);
    k_bn_apply<<<(Bn*CO*HW/4)/256, 256>>>(out);
}